// round 15
// baseline (speedup 1.0000x reference)
#include <cuda_runtime.h>
#include <cstdint>
#include <cstddef>

// Problem dims (fixed per reference)
#define BB_ 2048
#define NN_ 64
#define CC_ 256
#define FF_ 256
#define NEGV (-9.0e15f)

// -------- scratch (allocation-free: __device__ globals) --------
// H1 layout: [g=32][f=256][r=4096]  (g = batch-block of 64, r = (b%64)*64 + m), tf32 bits
__device__ uint32_t g_H1[BB_ * NN_ * FF_];
__device__ uint32_t g_adj[FF_ * NN_ * NN_];  // 4 MB: softmax adj as tf32 bits [f][n][m]
__device__ float    g_dT[NN_ * FF_];         // diag, transposed [n][f], f32
__device__ uint32_t g_WT[2 * FF_ * CC_];     // WcatT as tf32 bits [n=512][c=256]
__device__ int      g_mask_mode;             // 0=uint8, 1=int32, 2=float32

// -------- helpers --------
__device__ __forceinline__ uint32_t f2t(float x) {
    uint32_t r;
    asm("cvt.rna.tf32.f32 %0, %1;" : "=r"(r) : "f"(x));
    return r;
}

__device__ __forceinline__ void mma8(float* d, const uint32_t* a, const uint32_t* b) {
    asm volatile(
        "mma.sync.aligned.m16n8k8.row.col.f32.tf32.tf32.f32 "
        "{%0,%1,%2,%3}, {%4,%5,%6,%7}, {%8,%9}, {%0,%1,%2,%3};\n"
        : "+f"(d[0]), "+f"(d[1]), "+f"(d[2]), "+f"(d[3])
        : "r"(a[0]), "r"(a[1]), "r"(a[2]), "r"(a[3]), "r"(b[0]), "r"(b[1]));
}

__device__ __forceinline__ void ldsm4(uint32_t* r, uint32_t addr) {
    asm volatile("ldmatrix.sync.aligned.m8n8.x4.shared.b16 {%0,%1,%2,%3}, [%4];"
        : "=r"(r[0]), "=r"(r[1]), "=r"(r[2]), "=r"(r[3]) : "r"(addr));
}

__device__ __forceinline__ void cpa16(uint32_t dst, const void* src) {
    asm volatile("cp.async.cg.shared.global [%0], [%1], 16;" :: "r"(dst), "l"(src) : "memory");
}
__device__ __forceinline__ void cp_commit() {
    asm volatile("cp.async.commit_group;" ::: "memory");
}
__device__ __forceinline__ void cp_wait0() {
    asm volatile("cp.async.wait_group 0;" ::: "memory");
}
__device__ __forceinline__ void cp_wait1() {
    asm volatile("cp.async.wait_group 1;" ::: "memory");
}

extern __shared__ float sm_dyn[];

// -------- kernel 0: detect mask dtype --------
__global__ void k_detect(const int* __restrict__ m) {
    int all01 = 1, allf = 1;
    for (int i = threadIdx.x; i < 1024; i += 32) {
        int v = m[i];
        if (!(v == 0 || v == 1)) all01 = 0;
        if (!(v == 0 || v == 0x3F800000)) allf = 0;
    }
    #pragma unroll
    for (int s = 16; s > 0; s >>= 1) {
        all01 &= __shfl_xor_sync(0xffffffffu, all01, s);
        allf  &= __shfl_xor_sync(0xffffffffu, allf, s);
    }
    if (threadIdx.x == 0) g_mask_mode = all01 ? 1 : (allf ? 2 : 0);
}

// -------- kernel 1: WT[n][c] tf32: n<256 -> W1^T ; n>=256 -> (W0-W1)^T --------
__global__ void k_prep(const float* __restrict__ W) {
    int i = blockIdx.x * 256 + threadIdx.x;     // 131072 = 512*256
    int n = i >> 8, c = i & 255;
    float v;
    if (n < 256) {
        v = W[CC_ * FF_ + c * 256 + n];
    } else {
        int f = n - 256;
        v = W[c * 256 + f] - W[CC_ * FF_ + c * 256 + f];
    }
    g_WT[i] = f2t(v);
}

// -------- kernel 2: masked row-softmax -> adj (tf32 bits), diag -> dT (f32) --------
__global__ void k_softmax(const float* __restrict__ e, const void* __restrict__ maskp) {
    int w = threadIdx.x >> 5, lane = threadIdx.x & 31;
    int row = blockIdx.x * 8 + w;               // f*64+n
    int n = row & 63;

    int mode = g_mask_mode;
    bool m0, m1;
    if (mode == 1) {
        const int* mi = (const int*)maskp;
        m0 = mi[n * 64 + lane] != 0;
        m1 = mi[n * 64 + lane + 32] != 0;
    } else if (mode == 2) {
        const float* mf = (const float*)maskp;
        m0 = mf[n * 64 + lane] != 0.0f;
        m1 = mf[n * 64 + lane + 32] != 0.0f;
    } else {
        const unsigned char* mb = (const unsigned char*)maskp;
        m0 = mb[n * 64 + lane] != 0;
        m1 = mb[n * 64 + lane + 32] != 0;
    }

    const float* er = e + (size_t)row * 64;
    float v0 = m0 ? er[lane] : NEGV;
    float v1 = m1 ? er[lane + 32] : NEGV;

    float mx = fmaxf(v0, v1);
    #pragma unroll
    for (int s = 16; s > 0; s >>= 1) mx = fmaxf(mx, __shfl_xor_sync(0xffffffff, mx, s));

    float e0 = expf(v0 - mx);
    float e1 = expf(v1 - mx);
    float sum = e0 + e1;
    #pragma unroll
    for (int s = 16; s > 0; s >>= 1) sum += __shfl_xor_sync(0xffffffff, sum, s);
    float inv = 1.0f / sum;

    float a0 = e0 * inv, a1 = e1 * inv;
    g_adj[(size_t)row * 64 + lane] = f2t(a0);
    g_adj[(size_t)row * 64 + lane + 32] = f2t(a1);
    int f = row >> 6;
    if (lane == n)      g_dT[n * 256 + f] = a0;
    if (lane + 32 == n) g_dT[n * 256 + f] = a1;
}

// -------- kernel 3: tf32 GEMM  Y = X[131072,256] @ Wcat[256,512], 3-stage --------
// BM=128, BN=256, BK=16; 512 thr, 16 warps (4m x 4n), warp tile 32x64 (R8 geometry).
// 3-stage: B cp.async issued 2 tiles ahead (wait_group 1); A LDG'd 4 ahead (2 reg
// slots), STS'd 2 ahead. Per-tile cp stall removed.
#define GEMM_AB 8192
#define GEMM_BB 16384
#define GEMM_STG (GEMM_AB + GEMM_BB)      // 24576
#define GEMM_SMEM (3 * GEMM_STG)          // 73728 B

__global__ __launch_bounds__(512, 1) void k_gemm(const float* __restrict__ X,
                                                 const float* __restrict__ bias,
                                                 float* __restrict__ out) {
    char* smc = (char*)sm_dyn;
    const uint32_t sbase = (uint32_t)__cvta_generic_to_shared(sm_dyn);

    const int t = threadIdx.x, lane = t & 31, w = t >> 5;
    const int wm = w & 3, wn = w >> 2;
    const int rowBase = blockIdx.x * 128;
    const int nB = blockIdx.y * 256;

    // loaders
    const int ar = t >> 2, ac = t & 3;                  // A: row ar, chunk ac
    const int bn = t >> 1, bc0 = (t & 1) * 2;           // B: row bn, chunks bc0, bc0+1
    const float* gA = X + (size_t)(rowBase + ar) * 256 + ac * 4;
    const uint32_t* gB = g_WT + (size_t)(nB + bn) * 256 + bc0 * 4;
    const uint32_t aSts = (uint32_t)(ar * 64 + ((ac ^ ((ar >> 1) & 3)) * 16));
    const uint32_t bD0 = (uint32_t)(bn * 64 + ((bc0 ^ ((bn >> 1) & 3)) * 16));
    const uint32_t bD1 = (uint32_t)(bn * 64 + (((bc0 + 1) ^ ((bn >> 1) & 3)) * 16));

    // ldmatrix lane geometry
    const int amr = lane & 15, akh = lane >> 4;
    const int bnr = (lane & 7) + ((lane >> 4) << 3), bkh = (lane >> 3) & 1;

    float acc[2][8][4];
    #pragma unroll
    for (int i = 0; i < 2; i++)
        #pragma unroll
        for (int j = 0; j < 8; j++)
            #pragma unroll
            for (int r = 0; r < 4; r++) acc[i][j][r] = 0.0f;

    float4 va[2];

    // prologue: A0,A1 -> regs -> STS stages 0,1; B0,B1 cp.async; A2,A3 -> regs
    va[0] = __ldg((const float4*)(gA + 0));
    va[1] = __ldg((const float4*)(gA + 16));
    cpa16(sbase + 0 * GEMM_STG + GEMM_AB + bD0, gB);
    cpa16(sbase + 0 * GEMM_STG + GEMM_AB + bD1, gB + 4);
    cp_commit();
    cpa16(sbase + 1 * GEMM_STG + GEMM_AB + bD0, gB + 16);
    cpa16(sbase + 1 * GEMM_STG + GEMM_AB + bD1, gB + 20);
    cp_commit();
    #pragma unroll
    for (int s = 0; s < 2; s++) {
        uint4 u;
        u.x = f2t(va[s].x); u.y = f2t(va[s].y); u.z = f2t(va[s].z); u.w = f2t(va[s].w);
        *(uint4*)(smc + s * GEMM_STG + aSts) = u;
    }
    va[0] = __ldg((const float4*)(gA + 32));
    va[1] = __ldg((const float4*)(gA + 48));

    #pragma unroll 1
    for (int kt = 0; kt < 16; kt++) {
        const int stg = kt % 3;
        const uint32_t abase = sbase + stg * GEMM_STG;
        const uint32_t bbase = abase + GEMM_AB;

        if (kt < 15) cp_wait1(); else cp_wait0();
        __syncthreads();

        if (kt + 2 < 16) {
            const int ns = (kt + 2) % 3;
            const int sl = kt & 1;
            // STS A(kt+2)
            uint4 u;
            u.x = f2t(va[sl].x); u.y = f2t(va[sl].y); u.z = f2t(va[sl].z); u.w = f2t(va[sl].w);
            *(uint4*)(smc + ns * GEMM_STG + aSts) = u;
            // issue B(kt+2)
            const uint32_t* s = gB + (kt + 2) * 16;
            cpa16(sbase + ns * GEMM_STG + GEMM_AB + bD0, s);
            cpa16(sbase + ns * GEMM_STG + GEMM_AB + bD1, s + 4);
            cp_commit();
            // LDG A(kt+4)
            if (kt + 4 < 16)
                va[sl] = __ldg((const float4*)(gA + (kt + 4) * 16));
        }

        #pragma unroll
        for (int ks = 0; ks < 2; ks++) {
            uint32_t af[2][4];
            #pragma unroll
            for (int mt = 0; mt < 2; mt++) {
                int m = wm * 32 + mt * 16 + amr;
                int c = ks * 2 + akh;
                ldsm4(af[mt], abase + m * 64 + ((c ^ ((m >> 1) & 3)) * 16));
            }
            #pragma unroll
            for (int ntp = 0; ntp < 4; ntp++) {
                int nl = wn * 64 + ntp * 16 + bnr;
                int c = ks * 2 + bkh;
                uint32_t bb[4];
                ldsm4(bb, bbase + nl * 64 + ((c ^ ((nl >> 1) & 3)) * 16));
                mma8(acc[0][2 * ntp + 0], af[0], bb + 0);
                mma8(acc[1][2 * ntp + 0], af[1], bb + 0);
                mma8(acc[0][2 * ntp + 1], af[0], bb + 2);
                mma8(acc[1][2 * ntp + 1], af[1], bb + 2);
            }
        }
    }

    // epilogue
    const int g = rowBase >> 12;             // batch-block of 64 (4096 rows)
    #pragma unroll
    for (int mt = 0; mt < 2; mt++) {
        int gr0 = rowBase + wm * 32 + mt * 16 + (lane >> 2);
        #pragma unroll
        for (int nt = 0; nt < 8; nt++) {
            int gc = nB + wn * 64 + nt * 8 + (lane & 3) * 2;
            #pragma unroll
            for (int h = 0; h < 2; h++) {
                int gr = gr0 + h * 8;
                float v0 = acc[mt][nt][h * 2 + 0];
                float v1 = acc[mt][nt][h * 2 + 1];
                if (blockIdx.y == 0) {
                    // H1 blocked layout [g][f][r]: r = gr & 4095
                    int r = gr & 4095;
                    g_H1[((size_t)(g * 256 + gc)) * 4096 + r] = f2t(v0);
                    g_H1[((size_t)(g * 256 + gc + 1)) * 4096 + r] = f2t(v1);
                } else {
                    int f = gc - 256;
                    int n = gr & 63;
                    float o0 = v0 * __ldg(&g_dT[n * 256 + f]) + __ldg(&bias[f]);
                    float o1 = v1 * __ldg(&g_dT[n * 256 + f + 1]) + __ldg(&bias[f + 1]);
                    *(float2*)&out[(size_t)gr * 256 + f] = make_float2(o0, o1);
                }
            }
        }
    }
}

// -------- kernel 4: einsum  out[b,n,f] += sum_m adj[f,n,m] * H1[b,m,f]  (R8 exact) --------
// CTA = 64 batches x 4 channels; 256 thr, 8 warps, 2/channel, warp tile 32b x 64n.
// planes[ch][b=64][m=64w] AND adj[ch][n=64][m] both staged via cp.async.
// Cbuf (f32, reuses adj region) recombines 4 channels for float4 out RMW.
#define EIN_PLANE 16384
#define EIN_PLANES (4 * EIN_PLANE)            // 65536 B
#define EIN_ADJ   (4 * EIN_PLANE)             // 65536 B
#define EIN_SMEM  (EIN_PLANES + EIN_ADJ)      // 131072 B

__global__ __launch_bounds__(256, 1) void k_einsum(float* __restrict__ out) {
    char* smc = (char*)sm_dyn;
    const uint32_t sbase = (uint32_t)__cvta_generic_to_shared(sm_dyn);

    const int t = threadIdx.x, lane = t & 31, w = t >> 5;
    const int ch = w >> 1, bh = w & 1;          // warp's channel + b-half
    const int f0 = blockIdx.x * 4;
    const int g = blockIdx.y;                   // batch-block of 64
    const int B0 = g * 64;

    // ---- stage planes via cp.async: 4 ch x 64 b x 16 chunks = 4096 chunks ----
    #pragma unroll
    for (int j = 0; j < 16; j++) {
        int idx = j * 256 + t;
        int c4 = idx >> 10, rem = idx & 1023;     // rem = b*16 + c
        int b = rem >> 4, c = rem & 15;
        const uint32_t* src = g_H1 + ((size_t)(g * 256 + f0 + c4)) * 4096 + b * 64 + c * 4;
        uint32_t dst = sbase + c4 * EIN_PLANE + b * 256 + ((c ^ (b & 7)) * 16);
        cpa16(dst, src);
    }
    // ---- stage adj via cp.async: 4 ch x 64 n x 16 chunks ----
    #pragma unroll
    for (int j = 0; j < 16; j++) {
        int idx = j * 256 + t;
        int c4 = idx >> 10, rem = idx & 1023;
        int n = rem >> 4, c = rem & 15;
        const uint32_t* src = g_adj + (size_t)(f0 + c4) * 4096 + n * 64 + c * 4;
        uint32_t dst = sbase + EIN_PLANES + c4 * EIN_PLANE + n * 256 + ((c ^ (n & 7)) * 16);
        cpa16(dst, src);
    }
    cp_commit();
    cp_wait0();
    __syncthreads();

    // ---- mma: each warp = one channel, tile 32b x 64n over k=64 ----
    const uint32_t pbase = sbase + ch * EIN_PLANE;
    const uint32_t jbase = sbase + EIN_PLANES + ch * EIN_PLANE;
    const int amr = lane & 15, akh = lane >> 4;
    const int bnr = (lane & 7) + ((lane >> 4) << 3), bkh = (lane >> 3) & 1;

    float acc[2][8][4];
    #pragma unroll
    for (int i = 0; i < 2; i++)
        #pragma unroll
        for (int j = 0; j < 8; j++)
            #pragma unroll
            for (int r = 0; r < 4; r++) acc[i][j][r] = 0.0f;

    #pragma unroll
    for (int ks = 0; ks < 8; ks++) {
        uint32_t af[2][4];
        #pragma unroll
        for (int mt = 0; mt < 2; mt++) {
            int b = bh * 32 + mt * 16 + amr;
            int c = ks * 2 + akh;
            ldsm4(af[mt], pbase + b * 256 + ((c ^ (b & 7)) * 16));
        }
        #pragma unroll
        for (int ntp = 0; ntp < 4; ntp++) {
            int n = ntp * 16 + bnr;
            int c = ks * 2 + bkh;
            uint32_t bb[4];
            ldsm4(bb, jbase + n * 256 + ((c ^ (n & 7)) * 16));
            mma8(acc[0][2 * ntp + 0], af[0], bb + 0);
            mma8(acc[1][2 * ntp + 0], af[1], bb + 0);
            mma8(acc[0][2 * ntp + 1], af[0], bb + 2);
            mma8(acc[1][2 * ntp + 1], af[1], bb + 2);
        }
    }
    __syncthreads();   // all adj reads done; safe to overwrite adj region with Cbuf

    // ---- write acc -> Cbuf[ch][b][n] (f32, XOR-swizzled cols) ----
    float* Cbuf = (float*)(smc + EIN_PLANES);
    #pragma unroll
    for (int mt = 0; mt < 2; mt++) {
        #pragma unroll
        for (int h = 0; h < 2; h++) {
            int b = bh * 32 + mt * 16 + (lane >> 2) + h * 8;
            #pragma unroll
            for (int nt = 0; nt < 8; nt++) {
                int col = nt * 8 + (lane & 3) * 2;
                int colp = col ^ ((b & 3) << 3);
                *(float2*)&Cbuf[ch * 4096 + b * 64 + colp] =
                    make_float2(acc[mt][nt][h * 2 + 0], acc[mt][nt][h * 2 + 1]);
            }
        }
    }
    __syncthreads();

    // ---- final RMW: thread -> (b, 16 n's), float4 covering 4 channels ----
    {
        int b = t >> 2;
        int nb0 = (t & 3) * 16;
        #pragma unroll
        for (int i = 0; i < 16; i++) {
            int n = nb0 + i;
            int colp = n ^ ((b & 3) << 3);
            float c0 = Cbuf[0 * 4096 + b * 64 + colp];
            float c1 = Cbuf[1 * 4096 + b * 64 + colp];
            float c2 = Cbuf[2 * 4096 + b * 64 + colp];
            float c3 = Cbuf[3 * 4096 + b * 64 + colp];
            float* p = out + ((size_t)(B0 + b) * 64 + n) * 256 + f0;
            float4 o = *(float4*)p;
            o.x += c0; o.y += c1; o.z += c2; o.w += c3;
            *(float4*)p = o;
        }
    }
}

// -------- launch --------
extern "C" void kernel_launch(void* const* d_in, const int* in_sizes, int n_in,
                              void* d_out, int out_size) {
    const float* x = nullptr;
    const float* W = nullptr;
    const float* e = nullptr;
    const float* bias = nullptr;
    const void* mask = nullptr;
    for (int i = 0; i < n_in; i++) {
        switch (in_sizes[i]) {
            case 33554432: x = (const float*)d_in[i]; break;
            case 131072:   W = (const float*)d_in[i]; break;
            case 1048576:  e = (const float*)d_in[i]; break;
            case 256:      bias = (const float*)d_in[i]; break;
            case 4096:     mask = d_in[i]; break;
            default: break;
        }
    }
    float* out = (float*)d_out;

    cudaFuncSetAttribute(k_gemm, cudaFuncAttributeMaxDynamicSharedMemorySize, GEMM_SMEM);
    cudaFuncSetAttribute(k_einsum, cudaFuncAttributeMaxDynamicSharedMemorySize, EIN_SMEM);

    k_detect<<<1, 32>>>((const int*)mask);
    k_prep<<<512, 256>>>(W);
    k_softmax<<<2048, 256>>>(e, mask);
    k_gemm<<<dim3(1024, 2), 512, GEMM_SMEM>>>(x, bias, out);
    k_einsum<<<dim3(64, 32), 256, EIN_SMEM>>>(out);
}

// round 16
// speedup vs baseline: 1.1553x; 1.1553x over previous
#include <cuda_runtime.h>
#include <cstdint>
#include <cstddef>

// Problem dims (fixed per reference)
#define BB_ 2048
#define NN_ 64
#define CC_ 256
#define FF_ 256
#define NEGV (-9.0e15f)

// -------- scratch (allocation-free: __device__ globals) --------
// H1 layout: [g=32][f=256][r=4096]  (g = batch-block of 64, r = (b%64)*64 + m), tf32 bits
__device__ uint32_t g_H1[BB_ * NN_ * FF_];
__device__ uint32_t g_adj[FF_ * NN_ * NN_];  // 4 MB: softmax adj as tf32 bits [f][n][m]
__device__ float    g_dT[NN_ * FF_];         // diag, transposed [n][f], f32
__device__ uint32_t g_WT[2 * FF_ * CC_];     // WcatT as tf32 bits [n=512][c=256]
__device__ int      g_mask_mode;             // 0=uint8, 1=int32, 2=float32

// -------- helpers --------
__device__ __forceinline__ uint32_t f2t(float x) {
    uint32_t r;
    asm("cvt.rna.tf32.f32 %0, %1;" : "=r"(r) : "f"(x));
    return r;
}

__device__ __forceinline__ void mma8(float* d, const uint32_t* a, const uint32_t* b) {
    asm volatile(
        "mma.sync.aligned.m16n8k8.row.col.f32.tf32.tf32.f32 "
        "{%0,%1,%2,%3}, {%4,%5,%6,%7}, {%8,%9}, {%0,%1,%2,%3};\n"
        : "+f"(d[0]), "+f"(d[1]), "+f"(d[2]), "+f"(d[3])
        : "r"(a[0]), "r"(a[1]), "r"(a[2]), "r"(a[3]), "r"(b[0]), "r"(b[1]));
}

__device__ __forceinline__ void ldsm4(uint32_t* r, uint32_t addr) {
    asm volatile("ldmatrix.sync.aligned.m8n8.x4.shared.b16 {%0,%1,%2,%3}, [%4];"
        : "=r"(r[0]), "=r"(r[1]), "=r"(r[2]), "=r"(r[3]) : "r"(addr));
}

__device__ __forceinline__ void cpa16(uint32_t dst, const void* src) {
    asm volatile("cp.async.cg.shared.global [%0], [%1], 16;" :: "r"(dst), "l"(src) : "memory");
}
__device__ __forceinline__ void cp_commit() {
    asm volatile("cp.async.commit_group;" ::: "memory");
}
__device__ __forceinline__ void cp_wait0() {
    asm volatile("cp.async.wait_group 0;" ::: "memory");
}

extern __shared__ float sm_dyn[];

// -------- kernel 0: detect mask dtype --------
__global__ void k_detect(const int* __restrict__ m) {
    int all01 = 1, allf = 1;
    for (int i = threadIdx.x; i < 1024; i += 32) {
        int v = m[i];
        if (!(v == 0 || v == 1)) all01 = 0;
        if (!(v == 0 || v == 0x3F800000)) allf = 0;
    }
    #pragma unroll
    for (int s = 16; s > 0; s >>= 1) {
        all01 &= __shfl_xor_sync(0xffffffffu, all01, s);
        allf  &= __shfl_xor_sync(0xffffffffu, allf, s);
    }
    if (threadIdx.x == 0) g_mask_mode = all01 ? 1 : (allf ? 2 : 0);
}

// -------- kernel 1: WT[n][c] tf32: n<256 -> W1^T ; n>=256 -> (W0-W1)^T --------
__global__ void k_prep(const float* __restrict__ W) {
    int i = blockIdx.x * 256 + threadIdx.x;     // 131072 = 512*256
    int n = i >> 8, c = i & 255;
    float v;
    if (n < 256) {
        v = W[CC_ * FF_ + c * 256 + n];
    } else {
        int f = n - 256;
        v = W[c * 256 + f] - W[CC_ * FF_ + c * 256 + f];
    }
    g_WT[i] = f2t(v);
}

// -------- kernel 2: masked row-softmax -> adj (tf32 bits), diag -> dT (f32) --------
__global__ void k_softmax(const float* __restrict__ e, const void* __restrict__ maskp) {
    int w = threadIdx.x >> 5, lane = threadIdx.x & 31;
    int row = blockIdx.x * 8 + w;               // f*64+n
    int n = row & 63;

    int mode = g_mask_mode;
    bool m0, m1;
    if (mode == 1) {
        const int* mi = (const int*)maskp;
        m0 = mi[n * 64 + lane] != 0;
        m1 = mi[n * 64 + lane + 32] != 0;
    } else if (mode == 2) {
        const float* mf = (const float*)maskp;
        m0 = mf[n * 64 + lane] != 0.0f;
        m1 = mf[n * 64 + lane + 32] != 0.0f;
    } else {
        const unsigned char* mb = (const unsigned char*)maskp;
        m0 = mb[n * 64 + lane] != 0;
        m1 = mb[n * 64 + lane + 32] != 0;
    }

    const float* er = e + (size_t)row * 64;
    float v0 = m0 ? er[lane] : NEGV;
    float v1 = m1 ? er[lane + 32] : NEGV;

    float mx = fmaxf(v0, v1);
    #pragma unroll
    for (int s = 16; s > 0; s >>= 1) mx = fmaxf(mx, __shfl_xor_sync(0xffffffff, mx, s));

    float e0 = expf(v0 - mx);
    float e1 = expf(v1 - mx);
    float sum = e0 + e1;
    #pragma unroll
    for (int s = 16; s > 0; s >>= 1) sum += __shfl_xor_sync(0xffffffff, sum, s);
    float inv = 1.0f / sum;

    float a0 = e0 * inv, a1 = e1 * inv;
    g_adj[(size_t)row * 64 + lane] = f2t(a0);
    g_adj[(size_t)row * 64 + lane + 32] = f2t(a1);
    int f = row >> 6;
    if (lane == n)      g_dT[n * 256 + f] = a0;
    if (lane + 32 == n) g_dT[n * 256 + f] = a1;
}

// -------- kernel 3: tf32 GEMM  Y = X[131072,256] @ Wcat[256,512]  (R8 frozen) --------
// BM=128, BN=256, BK=16; 512 thr, 16 warps (4m x 4n), warp tile 32x64.
#define GEMM_AB 8192
#define GEMM_BB 16384
#define GEMM_BUF (GEMM_AB + GEMM_BB)
#define GEMM_SMEM (2 * GEMM_BUF)          // 49152 B

__global__ __launch_bounds__(512, 1) void k_gemm(const float* __restrict__ X,
                                                 const float* __restrict__ bias,
                                                 float* __restrict__ out) {
    char* smc = (char*)sm_dyn;
    const uint32_t sbase = (uint32_t)__cvta_generic_to_shared(sm_dyn);

    const int t = threadIdx.x, lane = t & 31, w = t >> 5;
    const int wm = w & 3, wn = w >> 2;
    const int rowBase = blockIdx.x * 128;
    const int nB = blockIdx.y * 256;

    // loaders
    const int ar = t >> 2, ac = t & 3;                  // A: row ar, chunk ac
    const int bn = t >> 1, bc0 = (t & 1) * 2;           // B: row bn, chunks bc0, bc0+1
    const float* gA = X + (size_t)(rowBase + ar) * 256 + ac * 4;
    const uint32_t* gB = g_WT + (size_t)(nB + bn) * 256 + bc0 * 4;
    const uint32_t aSts = (uint32_t)(ar * 64 + ((ac ^ ((ar >> 1) & 3)) * 16));
    const uint32_t bD0 = (uint32_t)(bn * 64 + ((bc0 ^ ((bn >> 1) & 3)) * 16));
    const uint32_t bD1 = (uint32_t)(bn * 64 + (((bc0 + 1) ^ ((bn >> 1) & 3)) * 16));

    // ldmatrix lane geometry
    const int amr = lane & 15, akh = lane >> 4;
    const int bnr = (lane & 7) + ((lane >> 4) << 3), bkh = (lane >> 3) & 1;

    float acc[2][8][4];
    #pragma unroll
    for (int i = 0; i < 2; i++)
        #pragma unroll
        for (int j = 0; j < 8; j++)
            #pragma unroll
            for (int r = 0; r < 4; r++) acc[i][j][r] = 0.0f;

    // prologue: B0 via cp.async, A0 via LDG+cvt+STS
    float4 va = __ldg((const float4*)gA);
    cpa16(sbase + GEMM_AB + bD0, gB);
    cpa16(sbase + GEMM_AB + bD1, gB + 4);
    cp_commit();
    {
        uint4 u;
        u.x = f2t(va.x); u.y = f2t(va.y); u.z = f2t(va.z); u.w = f2t(va.w);
        *(uint4*)(smc + aSts) = u;
    }

    #pragma unroll 1
    for (int kt = 0; kt < 16; kt++) {
        const int b = kt & 1;
        const uint32_t abase = sbase + b * GEMM_BUF;
        const uint32_t bbase = abase + GEMM_AB;

        if (kt < 15) va = __ldg((const float4*)(gA + (kt + 1) * 16));

        cp_wait0();
        __syncthreads();

        if (kt < 15) {
            const uint32_t nbB = sbase + (1 - b) * GEMM_BUF + GEMM_AB;
            const uint32_t* s = gB + (kt + 1) * 16;
            cpa16(nbB + bD0, s);
            cpa16(nbB + bD1, s + 4);
            cp_commit();
        }

        #pragma unroll
        for (int ks = 0; ks < 2; ks++) {
            uint32_t af[2][4];
            #pragma unroll
            for (int mt = 0; mt < 2; mt++) {
                int m = wm * 32 + mt * 16 + amr;
                int c = ks * 2 + akh;
                ldsm4(af[mt], abase + m * 64 + ((c ^ ((m >> 1) & 3)) * 16));
            }
            #pragma unroll
            for (int ntp = 0; ntp < 4; ntp++) {
                int nl = wn * 64 + ntp * 16 + bnr;
                int c = ks * 2 + bkh;
                uint32_t bb[4];
                ldsm4(bb, bbase + nl * 64 + ((c ^ ((nl >> 1) & 3)) * 16));
                mma8(acc[0][2 * ntp + 0], af[0], bb + 0);
                mma8(acc[1][2 * ntp + 0], af[1], bb + 0);
                mma8(acc[0][2 * ntp + 1], af[0], bb + 2);
                mma8(acc[1][2 * ntp + 1], af[1], bb + 2);
            }
        }

        if (kt < 15) {
            uint4 u;
            u.x = f2t(va.x); u.y = f2t(va.y); u.z = f2t(va.z); u.w = f2t(va.w);
            *(uint4*)(smc + (1 - b) * GEMM_BUF + aSts) = u;
        }
    }

    // epilogue
    const int g = rowBase >> 12;             // batch-block of 64 (4096 rows)
    #pragma unroll
    for (int mt = 0; mt < 2; mt++) {
        int gr0 = rowBase + wm * 32 + mt * 16 + (lane >> 2);
        #pragma unroll
        for (int nt = 0; nt < 8; nt++) {
            int gc = nB + wn * 64 + nt * 8 + (lane & 3) * 2;
            #pragma unroll
            for (int h = 0; h < 2; h++) {
                int gr = gr0 + h * 8;
                float v0 = acc[mt][nt][h * 2 + 0];
                float v1 = acc[mt][nt][h * 2 + 1];
                if (blockIdx.y == 0) {
                    // H1 blocked layout [g][f][r]: r = gr & 4095
                    int r = gr & 4095;
                    g_H1[((size_t)(g * 256 + gc)) * 4096 + r] = f2t(v0);
                    g_H1[((size_t)(g * 256 + gc + 1)) * 4096 + r] = f2t(v1);
                } else {
                    int f = gc - 256;
                    int n = gr & 63;
                    float o0 = v0 * __ldg(&g_dT[n * 256 + f]) + __ldg(&bias[f]);
                    float o1 = v1 * __ldg(&g_dT[n * 256 + f + 1]) + __ldg(&bias[f + 1]);
                    *(float2*)&out[(size_t)gr * 256 + f] = make_float2(o0, o1);
                }
            }
        }
    }
}

// -------- kernel 4: einsum  out[b,n,f] += sum_m adj[f,n,m] * H1[b,m,f] --------
// CTA = 32 batches x 8 channels; 256 thr, 8 warps = 1 warp/channel, warp tile 32b x 64n.
// Full 32B out-sector coverage (f-tile of 8) -> single-touch RMW per sector.
// planes[ch=8][b=32][m=64w] (8KB each) + adj[ch=8][n=64][m] (16KB each) via cp.async.
// Cbuf[ch][b=32][n=64] (64KB) reuses the planes region (each warp's slice = its own plane).
#define EINP8 8192                             // one channel plane: 32 x 256 B
#define EIN_PLANES (8 * EINP8)                 // 65536 B
#define EIN_ADJC 16384                         // one adj channel: 64 x 256 B
#define EIN_ADJ (8 * EIN_ADJC)                 // 131072 B
#define EIN_SMEM (EIN_PLANES + EIN_ADJ)        // 196608 B

__global__ __launch_bounds__(256, 1) void k_einsum(float* __restrict__ out) {
    char* smc = (char*)sm_dyn;
    const uint32_t sbase = (uint32_t)__cvta_generic_to_shared(sm_dyn);

    const int t = threadIdx.x, lane = t & 31, w = t >> 5;
    const int ch = w;                           // warp = one channel
    const int f0 = blockIdx.x * 8;
    const int bchunk = blockIdx.y;              // 0..63: 32-batch chunk
    const int g = bchunk >> 1;
    const int halfoff = (bchunk & 1) * 2048;    // row offset within g-block
    const int B0c = bchunk * 32;

    // ---- stage planes via cp.async: 8 ch x 32 b x 16 chunks = 4096 ----
    #pragma unroll
    for (int j = 0; j < 16; j++) {
        int idx = j * 256 + t;
        int c8 = idx >> 9, rem = idx & 511;       // rem = b*16 + c
        int b = rem >> 4, c = rem & 15;
        const uint32_t* src = g_H1 + ((size_t)(g * 256 + f0 + c8)) * 4096 + halfoff + b * 64 + c * 4;
        uint32_t dst = sbase + c8 * EINP8 + b * 256 + ((c ^ (b & 7)) * 16);
        cpa16(dst, src);
    }
    // ---- stage adj via cp.async: 8 ch x 64 n x 16 chunks = 8192 ----
    #pragma unroll
    for (int j = 0; j < 32; j++) {
        int idx = j * 256 + t;
        int c8 = idx >> 10, rem = idx & 1023;
        int n = rem >> 4, c = rem & 15;
        const uint32_t* src = g_adj + (size_t)(f0 + c8) * 4096 + n * 64 + c * 4;
        uint32_t dst = sbase + EIN_PLANES + c8 * EIN_ADJC + n * 256 + ((c ^ (n & 7)) * 16);
        cpa16(dst, src);
    }
    cp_commit();
    cp_wait0();
    __syncthreads();

    // ---- mma: warp ch, tile 32b x 64n over k=64 ----
    const uint32_t pbase = sbase + ch * EINP8;
    const uint32_t jbase = sbase + EIN_PLANES + ch * EIN_ADJC;
    const int amr = lane & 15, akh = lane >> 4;
    const int bnr = (lane & 7) + ((lane >> 4) << 3), bkh = (lane >> 3) & 1;

    float acc[2][8][4];
    #pragma unroll
    for (int i = 0; i < 2; i++)
        #pragma unroll
        for (int j = 0; j < 8; j++)
            #pragma unroll
            for (int r = 0; r < 4; r++) acc[i][j][r] = 0.0f;

    #pragma unroll
    for (int ks = 0; ks < 8; ks++) {
        uint32_t af[2][4];
        #pragma unroll
        for (int mt = 0; mt < 2; mt++) {
            int b = mt * 16 + amr;               // 0..31 within chunk
            int c = ks * 2 + akh;
            ldsm4(af[mt], pbase + b * 256 + ((c ^ (b & 7)) * 16));
        }
        #pragma unroll
        for (int ntp = 0; ntp < 4; ntp++) {
            int n = ntp * 16 + bnr;
            int c = ks * 2 + bkh;
            uint32_t bb[4];
            ldsm4(bb, jbase + n * 256 + ((c ^ (n & 7)) * 16));
            mma8(acc[0][2 * ntp + 0], af[0], bb + 0);
            mma8(acc[1][2 * ntp + 0], af[1], bb + 0);
            mma8(acc[0][2 * ntp + 1], af[0], bb + 2);
            mma8(acc[1][2 * ntp + 1], af[1], bb + 2);
        }
    }
    __syncthreads();   // all plane reads done; planes region becomes Cbuf

    // ---- write acc -> Cbuf[ch][b=32][n=64] (f32, XOR-swizzled cols) ----
    float* Cbuf = (float*)smc;
    #pragma unroll
    for (int mt = 0; mt < 2; mt++) {
        #pragma unroll
        for (int h = 0; h < 2; h++) {
            int b = mt * 16 + (lane >> 2) + h * 8;
            #pragma unroll
            for (int nt = 0; nt < 8; nt++) {
                int col = nt * 8 + (lane & 3) * 2;
                int colp = col ^ ((b & 3) << 3);
                *(float2*)&Cbuf[ch * 2048 + b * 64 + colp] =
                    make_float2(acc[mt][nt][h * 2 + 0], acc[mt][nt][h * 2 + 1]);
            }
        }
    }
    __syncthreads();

    // ---- final RMW: thread -> (b, 8 n's), full 32B-sector float4-pair over 8 channels ----
    {
        int b = t >> 3;                     // 0..31
        int n0 = (t & 7) * 8;
        #pragma unroll
        for (int i = 0; i < 8; i++) {
            int n = n0 + i;
            int colp = n ^ ((b & 3) << 3);
            float c0 = Cbuf[0 * 2048 + b * 64 + colp];
            float c1 = Cbuf[1 * 2048 + b * 64 + colp];
            float c2 = Cbuf[2 * 2048 + b * 64 + colp];
            float c3 = Cbuf[3 * 2048 + b * 64 + colp];
            float c4 = Cbuf[4 * 2048 + b * 64 + colp];
            float c5 = Cbuf[5 * 2048 + b * 64 + colp];
            float c6 = Cbuf[6 * 2048 + b * 64 + colp];
            float c7 = Cbuf[7 * 2048 + b * 64 + colp];
            float* p = out + ((size_t)(B0c + b) * 64 + n) * 256 + f0;
            float4 o0 = *(float4*)p;
            float4 o1 = *(float4*)(p + 4);
            o0.x += c0; o0.y += c1; o0.z += c2; o0.w += c3;
            o1.x += c4; o1.y += c5; o1.z += c6; o1.w += c7;
            *(float4*)p = o0;
            *(float4*)(p + 4) = o1;
        }
    }
}

// -------- launch --------
extern "C" void kernel_launch(void* const* d_in, const int* in_sizes, int n_in,
                              void* d_out, int out_size) {
    const float* x = nullptr;
    const float* W = nullptr;
    const float* e = nullptr;
    const float* bias = nullptr;
    const void* mask = nullptr;
    for (int i = 0; i < n_in; i++) {
        switch (in_sizes[i]) {
            case 33554432: x = (const float*)d_in[i]; break;
            case 131072:   W = (const float*)d_in[i]; break;
            case 1048576:  e = (const float*)d_in[i]; break;
            case 256:      bias = (const float*)d_in[i]; break;
            case 4096:     mask = d_in[i]; break;
            default: break;
        }
    }
    float* out = (float*)d_out;

    cudaFuncSetAttribute(k_gemm, cudaFuncAttributeMaxDynamicSharedMemorySize, GEMM_SMEM);
    cudaFuncSetAttribute(k_einsum, cudaFuncAttributeMaxDynamicSharedMemorySize, EIN_SMEM);

    k_detect<<<1, 32>>>((const int*)mask);
    k_prep<<<512, 256>>>(W);
    k_softmax<<<2048, 256>>>(e, mask);
    k_gemm<<<dim3(1024, 2), 512, GEMM_SMEM>>>(x, bias, out);
    k_einsum<<<dim3(32, 64), 256, EIN_SMEM>>>(out);
}

// round 17
// speedup vs baseline: 1.1671x; 1.0102x over previous
#include <cuda_runtime.h>
#include <cstdint>
#include <cstddef>

// Problem dims (fixed per reference)
#define BB_ 2048
#define NN_ 64
#define CC_ 256
#define FF_ 256
#define NEGV (-9.0e15f)

// -------- scratch (allocation-free: __device__ globals) --------
// H1 layout: [g=32][f=256][r=4096]  (g = batch-block of 64, r = (b%64)*64 + m), tf32 bits
__device__ uint32_t g_H1[BB_ * NN_ * FF_];
__device__ uint32_t g_adj[FF_ * NN_ * NN_];  // 4 MB: softmax adj as tf32 bits [f][n][m]
__device__ float    g_dT[NN_ * FF_];         // diag, transposed [n][f], f32
__device__ uint32_t g_WT[2 * FF_ * CC_];     // WcatT as tf32 bits [n=512][c=256]
__device__ int      g_mask_mode;             // 0=uint8, 1=int32, 2=float32

// -------- helpers --------
__device__ __forceinline__ uint32_t f2t(float x) {
    uint32_t r;
    asm("cvt.rna.tf32.f32 %0, %1;" : "=r"(r) : "f"(x));
    return r;
}

__device__ __forceinline__ void mma8(float* d, const uint32_t* a, const uint32_t* b) {
    asm volatile(
        "mma.sync.aligned.m16n8k8.row.col.f32.tf32.tf32.f32 "
        "{%0,%1,%2,%3}, {%4,%5,%6,%7}, {%8,%9}, {%0,%1,%2,%3};\n"
        : "+f"(d[0]), "+f"(d[1]), "+f"(d[2]), "+f"(d[3])
        : "r"(a[0]), "r"(a[1]), "r"(a[2]), "r"(a[3]), "r"(b[0]), "r"(b[1]));
}

__device__ __forceinline__ void ldsm4(uint32_t* r, uint32_t addr) {
    asm volatile("ldmatrix.sync.aligned.m8n8.x4.shared.b16 {%0,%1,%2,%3}, [%4];"
        : "=r"(r[0]), "=r"(r[1]), "=r"(r[2]), "=r"(r[3]) : "r"(addr));
}

__device__ __forceinline__ void cpa16(uint32_t dst, const void* src) {
    asm volatile("cp.async.cg.shared.global [%0], [%1], 16;" :: "r"(dst), "l"(src) : "memory");
}
__device__ __forceinline__ void cp_commit() {
    asm volatile("cp.async.commit_group;" ::: "memory");
}
__device__ __forceinline__ void cp_wait0() {
    asm volatile("cp.async.wait_group 0;" ::: "memory");
}

extern __shared__ float sm_dyn[];

// -------- kernel 0: detect mask dtype --------
__global__ void k_detect(const int* __restrict__ m) {
    int all01 = 1, allf = 1;
    for (int i = threadIdx.x; i < 1024; i += 32) {
        int v = m[i];
        if (!(v == 0 || v == 1)) all01 = 0;
        if (!(v == 0 || v == 0x3F800000)) allf = 0;
    }
    #pragma unroll
    for (int s = 16; s > 0; s >>= 1) {
        all01 &= __shfl_xor_sync(0xffffffffu, all01, s);
        allf  &= __shfl_xor_sync(0xffffffffu, allf, s);
    }
    if (threadIdx.x == 0) g_mask_mode = all01 ? 1 : (allf ? 2 : 0);
}

// -------- kernel 1: WT[n][c] tf32: n<256 -> W1^T ; n>=256 -> (W0-W1)^T --------
__global__ void k_prep(const float* __restrict__ W) {
    int i = blockIdx.x * 256 + threadIdx.x;     // 131072 = 512*256
    int n = i >> 8, c = i & 255;
    float v;
    if (n < 256) {
        v = W[CC_ * FF_ + c * 256 + n];
    } else {
        int f = n - 256;
        v = W[c * 256 + f] - W[CC_ * FF_ + c * 256 + f];
    }
    g_WT[i] = f2t(v);
}

// -------- kernel 2: masked row-softmax -> adj (tf32 bits), diag -> dT (f32) --------
__global__ void k_softmax(const float* __restrict__ e, const void* __restrict__ maskp) {
    int w = threadIdx.x >> 5, lane = threadIdx.x & 31;
    int row = blockIdx.x * 8 + w;               // f*64+n
    int n = row & 63;

    int mode = g_mask_mode;
    bool m0, m1;
    if (mode == 1) {
        const int* mi = (const int*)maskp;
        m0 = mi[n * 64 + lane] != 0;
        m1 = mi[n * 64 + lane + 32] != 0;
    } else if (mode == 2) {
        const float* mf = (const float*)maskp;
        m0 = mf[n * 64 + lane] != 0.0f;
        m1 = mf[n * 64 + lane + 32] != 0.0f;
    } else {
        const unsigned char* mb = (const unsigned char*)maskp;
        m0 = mb[n * 64 + lane] != 0;
        m1 = mb[n * 64 + lane + 32] != 0;
    }

    const float* er = e + (size_t)row * 64;
    float v0 = m0 ? er[lane] : NEGV;
    float v1 = m1 ? er[lane + 32] : NEGV;

    float mx = fmaxf(v0, v1);
    #pragma unroll
    for (int s = 16; s > 0; s >>= 1) mx = fmaxf(mx, __shfl_xor_sync(0xffffffff, mx, s));

    float e0 = expf(v0 - mx);
    float e1 = expf(v1 - mx);
    float sum = e0 + e1;
    #pragma unroll
    for (int s = 16; s > 0; s >>= 1) sum += __shfl_xor_sync(0xffffffff, sum, s);
    float inv = 1.0f / sum;

    float a0 = e0 * inv, a1 = e1 * inv;
    g_adj[(size_t)row * 64 + lane] = f2t(a0);
    g_adj[(size_t)row * 64 + lane + 32] = f2t(a1);
    int f = row >> 6;
    if (lane == n)      g_dT[n * 256 + f] = a0;
    if (lane + 32 == n) g_dT[n * 256 + f] = a1;
}

// -------- kernel 3: tf32 GEMM  Y = X[131072,256] @ Wcat[256,512]  (R8 frozen) --------
// BM=128, BN=256, BK=16; 512 thr, 16 warps (4m x 4n), warp tile 32x64.
#define GEMM_AB 8192
#define GEMM_BB 16384
#define GEMM_BUF (GEMM_AB + GEMM_BB)
#define GEMM_SMEM (2 * GEMM_BUF)          // 49152 B

__global__ __launch_bounds__(512, 1) void k_gemm(const float* __restrict__ X,
                                                 const float* __restrict__ bias,
                                                 float* __restrict__ out) {
    char* smc = (char*)sm_dyn;
    const uint32_t sbase = (uint32_t)__cvta_generic_to_shared(sm_dyn);

    const int t = threadIdx.x, lane = t & 31, w = t >> 5;
    const int wm = w & 3, wn = w >> 2;
    const int rowBase = blockIdx.x * 128;
    const int nB = blockIdx.y * 256;

    // loaders
    const int ar = t >> 2, ac = t & 3;                  // A: row ar, chunk ac
    const int bn = t >> 1, bc0 = (t & 1) * 2;           // B: row bn, chunks bc0, bc0+1
    const float* gA = X + (size_t)(rowBase + ar) * 256 + ac * 4;
    const uint32_t* gB = g_WT + (size_t)(nB + bn) * 256 + bc0 * 4;
    const uint32_t aSts = (uint32_t)(ar * 64 + ((ac ^ ((ar >> 1) & 3)) * 16));
    const uint32_t bD0 = (uint32_t)(bn * 64 + ((bc0 ^ ((bn >> 1) & 3)) * 16));
    const uint32_t bD1 = (uint32_t)(bn * 64 + (((bc0 + 1) ^ ((bn >> 1) & 3)) * 16));

    // ldmatrix lane geometry
    const int amr = lane & 15, akh = lane >> 4;
    const int bnr = (lane & 7) + ((lane >> 4) << 3), bkh = (lane >> 3) & 1;

    float acc[2][8][4];
    #pragma unroll
    for (int i = 0; i < 2; i++)
        #pragma unroll
        for (int j = 0; j < 8; j++)
            #pragma unroll
            for (int r = 0; r < 4; r++) acc[i][j][r] = 0.0f;

    // prologue: B0 via cp.async, A0 via LDG+cvt+STS
    float4 va = __ldg((const float4*)gA);
    cpa16(sbase + GEMM_AB + bD0, gB);
    cpa16(sbase + GEMM_AB + bD1, gB + 4);
    cp_commit();
    {
        uint4 u;
        u.x = f2t(va.x); u.y = f2t(va.y); u.z = f2t(va.z); u.w = f2t(va.w);
        *(uint4*)(smc + aSts) = u;
    }

    #pragma unroll 1
    for (int kt = 0; kt < 16; kt++) {
        const int b = kt & 1;
        const uint32_t abase = sbase + b * GEMM_BUF;
        const uint32_t bbase = abase + GEMM_AB;

        if (kt < 15) va = __ldg((const float4*)(gA + (kt + 1) * 16));

        cp_wait0();
        __syncthreads();

        if (kt < 15) {
            const uint32_t nbB = sbase + (1 - b) * GEMM_BUF + GEMM_AB;
            const uint32_t* s = gB + (kt + 1) * 16;
            cpa16(nbB + bD0, s);
            cpa16(nbB + bD1, s + 4);
            cp_commit();
        }

        #pragma unroll
        for (int ks = 0; ks < 2; ks++) {
            uint32_t af[2][4];
            #pragma unroll
            for (int mt = 0; mt < 2; mt++) {
                int m = wm * 32 + mt * 16 + amr;
                int c = ks * 2 + akh;
                ldsm4(af[mt], abase + m * 64 + ((c ^ ((m >> 1) & 3)) * 16));
            }
            #pragma unroll
            for (int ntp = 0; ntp < 4; ntp++) {
                int nl = wn * 64 + ntp * 16 + bnr;
                int c = ks * 2 + bkh;
                uint32_t bb[4];
                ldsm4(bb, bbase + nl * 64 + ((c ^ ((nl >> 1) & 3)) * 16));
                mma8(acc[0][2 * ntp + 0], af[0], bb + 0);
                mma8(acc[1][2 * ntp + 0], af[1], bb + 0);
                mma8(acc[0][2 * ntp + 1], af[0], bb + 2);
                mma8(acc[1][2 * ntp + 1], af[1], bb + 2);
            }
        }

        if (kt < 15) {
            uint4 u;
            u.x = f2t(va.x); u.y = f2t(va.y); u.z = f2t(va.z); u.w = f2t(va.w);
            *(uint4*)(smc + (1 - b) * GEMM_BUF + aSts) = u;
        }
    }

    // epilogue
    const int g = rowBase >> 12;             // batch-block of 64 (4096 rows)
    #pragma unroll
    for (int mt = 0; mt < 2; mt++) {
        int gr0 = rowBase + wm * 32 + mt * 16 + (lane >> 2);
        #pragma unroll
        for (int nt = 0; nt < 8; nt++) {
            int gc = nB + wn * 64 + nt * 8 + (lane & 3) * 2;
            #pragma unroll
            for (int h = 0; h < 2; h++) {
                int gr = gr0 + h * 8;
                float v0 = acc[mt][nt][h * 2 + 0];
                float v1 = acc[mt][nt][h * 2 + 1];
                if (blockIdx.y == 0) {
                    // H1 blocked layout [g][f][r]: r = gr & 4095
                    int r = gr & 4095;
                    g_H1[((size_t)(g * 256 + gc)) * 4096 + r] = f2t(v0);
                    g_H1[((size_t)(g * 256 + gc + 1)) * 4096 + r] = f2t(v1);
                } else {
                    int f = gc - 256;
                    int n = gr & 63;
                    float o0 = v0 * __ldg(&g_dT[n * 256 + f]) + __ldg(&bias[f]);
                    float o1 = v1 * __ldg(&g_dT[n * 256 + f + 1]) + __ldg(&bias[f + 1]);
                    *(float2*)&out[(size_t)gr * 256 + f] = make_float2(o0, o1);
                }
            }
        }
    }
}

// -------- kernel 4: einsum  out[b,n,f] += sum_m adj[f,n,m] * H1[b,m,f] --------
// CTA = 32 batches x 8 channels; 512 thr, 16 warps = 2 warps/channel (n-halves),
// warp tile 32b x 32n. Full 32B out-sector coverage (f-tile of 8).
// planes[ch=8][b=32][m=64w] (8KB each) + adj[ch=8][n=64][m] (16KB each) via cp.async.
// Cbuf[ch][b=32][n=64] (64KB) reuses the planes region.
#define EINP8 8192                             // one channel plane: 32 x 256 B
#define EIN_PLANES (8 * EINP8)                 // 65536 B
#define EIN_ADJC 16384                         // one adj channel: 64 x 256 B
#define EIN_ADJ (8 * EIN_ADJC)                 // 131072 B
#define EIN_SMEM (EIN_PLANES + EIN_ADJ)        // 196608 B

__global__ __launch_bounds__(512, 1) void k_einsum(float* __restrict__ out) {
    char* smc = (char*)sm_dyn;
    const uint32_t sbase = (uint32_t)__cvta_generic_to_shared(sm_dyn);

    const int t = threadIdx.x, lane = t & 31, w = t >> 5;
    const int ch = w >> 1, nh = w & 1;          // channel + n-half
    const int f0 = blockIdx.x * 8;
    const int bchunk = blockIdx.y;              // 0..63: 32-batch chunk
    const int g = bchunk >> 1;
    const int halfoff = (bchunk & 1) * 2048;    // row offset within g-block
    const int B0c = bchunk * 32;

    // ---- stage planes via cp.async: 8 ch x 32 b x 16 chunks = 4096 ----
    #pragma unroll
    for (int j = 0; j < 8; j++) {
        int idx = j * 512 + t;
        int c8 = idx >> 9, rem = idx & 511;       // rem = b*16 + c
        int b = rem >> 4, c = rem & 15;
        const uint32_t* src = g_H1 + ((size_t)(g * 256 + f0 + c8)) * 4096 + halfoff + b * 64 + c * 4;
        uint32_t dst = sbase + c8 * EINP8 + b * 256 + ((c ^ (b & 7)) * 16);
        cpa16(dst, src);
    }
    // ---- stage adj via cp.async: 8 ch x 64 n x 16 chunks = 8192 ----
    #pragma unroll
    for (int j = 0; j < 16; j++) {
        int idx = j * 512 + t;
        int c8 = idx >> 10, rem = idx & 1023;
        int n = rem >> 4, c = rem & 15;
        const uint32_t* src = g_adj + (size_t)(f0 + c8) * 4096 + n * 64 + c * 4;
        uint32_t dst = sbase + EIN_PLANES + c8 * EIN_ADJC + n * 256 + ((c ^ (n & 7)) * 16);
        cpa16(dst, src);
    }
    cp_commit();
    cp_wait0();
    __syncthreads();

    // ---- mma: warp (ch, nh), tile 32b x 32n over k=64 ----
    const uint32_t pbase = sbase + ch * EINP8;
    const uint32_t jbase = sbase + EIN_PLANES + ch * EIN_ADJC;
    const int amr = lane & 15, akh = lane >> 4;
    const int bnr = (lane & 7) + ((lane >> 4) << 3), bkh = (lane >> 3) & 1;

    float acc[2][4][4];
    #pragma unroll
    for (int i = 0; i < 2; i++)
        #pragma unroll
        for (int j = 0; j < 4; j++)
            #pragma unroll
            for (int r = 0; r < 4; r++) acc[i][j][r] = 0.0f;

    #pragma unroll
    for (int ks = 0; ks < 8; ks++) {
        uint32_t af[2][4];
        #pragma unroll
        for (int mt = 0; mt < 2; mt++) {
            int b = mt * 16 + amr;               // 0..31 within chunk
            int c = ks * 2 + akh;
            ldsm4(af[mt], pbase + b * 256 + ((c ^ (b & 7)) * 16));
        }
        #pragma unroll
        for (int ntp = 0; ntp < 2; ntp++) {
            int n = nh * 32 + ntp * 16 + bnr;
            int c = ks * 2 + bkh;
            uint32_t bb[4];
            ldsm4(bb, jbase + n * 256 + ((c ^ (n & 7)) * 16));
            mma8(acc[0][2 * ntp + 0], af[0], bb + 0);
            mma8(acc[1][2 * ntp + 0], af[1], bb + 0);
            mma8(acc[0][2 * ntp + 1], af[0], bb + 2);
            mma8(acc[1][2 * ntp + 1], af[1], bb + 2);
        }
    }
    __syncthreads();   // all plane reads done; planes region becomes Cbuf

    // ---- write acc -> Cbuf[ch][b=32][n=64] (f32, XOR-swizzled cols) ----
    float* Cbuf = (float*)smc;
    #pragma unroll
    for (int mt = 0; mt < 2; mt++) {
        #pragma unroll
        for (int h = 0; h < 2; h++) {
            int b = mt * 16 + (lane >> 2) + h * 8;
            #pragma unroll
            for (int nt = 0; nt < 4; nt++) {
                int col = nh * 32 + nt * 8 + (lane & 3) * 2;
                int colp = col ^ ((b & 3) << 3);
                *(float2*)&Cbuf[ch * 2048 + b * 64 + colp] =
                    make_float2(acc[mt][nt][h * 2 + 0], acc[mt][nt][h * 2 + 1]);
            }
        }
    }
    __syncthreads();

    // ---- final RMW: thread -> (b, 4 n's), full 32B-sector float4-pair over 8 channels ----
    {
        int b = t >> 4;                     // 0..31
        int n0 = (t & 15) * 4;
        #pragma unroll
        for (int i = 0; i < 4; i++) {
            int n = n0 + i;
            int colp = n ^ ((b & 3) << 3);
            float c0 = Cbuf[0 * 2048 + b * 64 + colp];
            float c1 = Cbuf[1 * 2048 + b * 64 + colp];
            float c2 = Cbuf[2 * 2048 + b * 64 + colp];
            float c3 = Cbuf[3 * 2048 + b * 64 + colp];
            float c4 = Cbuf[4 * 2048 + b * 64 + colp];
            float c5 = Cbuf[5 * 2048 + b * 64 + colp];
            float c6 = Cbuf[6 * 2048 + b * 64 + colp];
            float c7 = Cbuf[7 * 2048 + b * 64 + colp];
            float* p = out + ((size_t)(B0c + b) * 64 + n) * 256 + f0;
            float4 o0 = *(float4*)p;
            float4 o1 = *(float4*)(p + 4);
            o0.x += c0; o0.y += c1; o0.z += c2; o0.w += c3;
            o1.x += c4; o1.y += c5; o1.z += c6; o1.w += c7;
            *(float4*)p = o0;
            *(float4*)(p + 4) = o1;
        }
    }
}

// -------- launch --------
extern "C" void kernel_launch(void* const* d_in, const int* in_sizes, int n_in,
                              void* d_out, int out_size) {
    const float* x = nullptr;
    const float* W = nullptr;
    const float* e = nullptr;
    const float* bias = nullptr;
    const void* mask = nullptr;
    for (int i = 0; i < n_in; i++) {
        switch (in_sizes[i]) {
            case 33554432: x = (const float*)d_in[i]; break;
            case 131072:   W = (const float*)d_in[i]; break;
            case 1048576:  e = (const float*)d_in[i]; break;
            case 256:      bias = (const float*)d_in[i]; break;
            case 4096:     mask = d_in[i]; break;
            default: break;
        }
    }
    float* out = (float*)d_out;

    cudaFuncSetAttribute(k_gemm, cudaFuncAttributeMaxDynamicSharedMemorySize, GEMM_SMEM);
    cudaFuncSetAttribute(k_einsum, cudaFuncAttributeMaxDynamicSharedMemorySize, EIN_SMEM);

    k_detect<<<1, 32>>>((const int*)mask);
    k_prep<<<512, 256>>>(W);
    k_softmax<<<2048, 256>>>(e, mask);
    k_gemm<<<dim3(1024, 2), 512, GEMM_SMEM>>>(x, bias, out);
    k_einsum<<<dim3(32, 64), 512, EIN_SMEM>>>(out);
}